// round 10
// baseline (speedup 1.0000x reference)
#include <cuda_runtime.h>

// MoE conditional FFN: T=16, TOP_K=2, E=8, H=1024, I=2816, fp32.
// Expert-major grouping: each used expert's weights stream from HBM once.
//
// R6: phase2's pair-loop operand (h) moves from L2 (~250cyc, serial stalls)
// into SHARED memory staged cooperatively per block (chunks of 4 pairs, 45KB).
// Weight row stays front-batched in registers (22 float4 = proven HBM recipe).
// Phase1 already at the LTS cap (6.45 TB/s) - unchanged.

#define NTOK   16
#define TOPK   2
#define NPAIR  (NTOK * TOPK)       // 32
#define HID    1024
#define INTER  2816
#define NEXP   8

__device__ float g_h[NPAIR * INTER];   // 360 KB scratch

__device__ __forceinline__ float dot4(float4 a, float4 b, float acc) {
    acc = fmaf(a.x, b.x, acc);
    acc = fmaf(a.y, b.y, acc);
    acc = fmaf(a.z, b.z, acc);
    return fmaf(a.w, b.w, acc);
}

// ---------------------------------------------------------------------------
// Phase 1 (R1's proven version, 28.5us = 6.45 TB/s): gate & down GEMVs + SiLU.
// grid = (INTER/32, NEXP), block = 256 (8 warps). Warp handles 4 rows; per row
// preloads 8+8 float4 weights into registers; pair loop reads x from L1.
// ---------------------------------------------------------------------------
__global__ __launch_bounds__(256, 2)
void moe_phase1(const float* __restrict__ x,        // [T, H]
                const int*   __restrict__ eidx,     // [T, TOPK]
                const float* __restrict__ gate,     // [E, I, H]
                const float* __restrict__ down)     // [E, I, H]
{
    const int e = blockIdx.y;

    __shared__ int s_cnt;
    __shared__ int s_pair[NPAIR];
    if (threadIdx.x == 0) {
        int c = 0;
        #pragma unroll
        for (int i = 0; i < NPAIR; i++)
            if (eidx[i] == e) s_pair[c++] = i;
        s_cnt = c;
    }
    __syncthreads();
    const int cnt = s_cnt;
    if (cnt == 0) return;

    const int warp = threadIdx.x >> 5;
    const int lane = threadIdx.x & 31;
    const int row0 = blockIdx.x * 32 + warp * 4;

    const float4* gate4 = reinterpret_cast<const float4*>(gate + (size_t)e * INTER * HID);
    const float4* down4 = reinterpret_cast<const float4*>(down + (size_t)e * INTER * HID);

    for (int rr = 0; rr < 4; rr++) {
        const int row = row0 + rr;
        const float4* gr = gate4 + (size_t)row * (HID / 4);
        const float4* dr = down4 + (size_t)row * (HID / 4);

        float4 g4[8], d4[8];
        #pragma unroll
        for (int j = 0; j < 8; j++) {
            g4[j] = gr[lane + 32 * j];
            d4[j] = dr[lane + 32 * j];
        }

        for (int p = 0; p < cnt; p++) {
            const int pa = s_pair[p];
            const int t  = pa >> 1;
            const float4* xr = reinterpret_cast<const float4*>(x + (size_t)t * HID);

            float ag = 0.f, ad = 0.f;
            #pragma unroll
            for (int j = 0; j < 8; j++) {
                const float4 x4 = xr[lane + 32 * j];
                ag = dot4(g4[j], x4, ag);
                ad = dot4(d4[j], x4, ad);
            }
            #pragma unroll
            for (int off = 16; off; off >>= 1) {
                ag += __shfl_xor_sync(0xFFFFFFFFu, ag, off);
                ad += __shfl_xor_sync(0xFFFFFFFFu, ad, off);
            }
            if (lane == 0) {
                const float s = ag / (1.f + __expf(-ag));   // silu(gate)
                g_h[(size_t)pa * INTER + row] = s * ad;
            }
        }
    }
}

// ---------------------------------------------------------------------------
// Phase 2: out[pair,hh] = up[e,hh,:] . h[pair,:]
// grid = (HID/8, NEXP) = 1024 blocks, block = 256 (8 warps). Warp = one row.
// Full weight row (22 float4/lane) preloaded once into registers. Pairs are
// processed in chunks of <=4; each chunk's h rows are cooperatively staged
// into SHARED memory (coalesced block copy), then consumed via LDS (29 cyc)
// instead of scattered L2 reads (~250 cyc).
// ---------------------------------------------------------------------------
#define CHUNK 4

__global__ __launch_bounds__(256, 2)
void moe_phase2(const int*   __restrict__ eidx,     // [T, TOPK]
                const float* __restrict__ up,       // [E, H, I]
                float*       __restrict__ out)      // [T, TOPK, H]
{
    const int e = blockIdx.y;

    __shared__ float s_h[CHUNK * INTER];            // 45056 B
    __shared__ int s_cnt;
    __shared__ int s_pair[NPAIR];

    const int tid = threadIdx.x;
    if (tid == 0) {
        int c = 0;
        #pragma unroll
        for (int i = 0; i < NPAIR; i++)
            if (eidx[i] == e) s_pair[c++] = i;
        s_cnt = c;
    }
    __syncthreads();
    const int cnt = s_cnt;
    if (cnt == 0) return;

    const int warp = tid >> 5;
    const int lane = tid & 31;
    const int hh   = blockIdx.x * 8 + warp;

    const float4* ur = reinterpret_cast<const float4*>(up + (size_t)e * HID * INTER)
                       + (size_t)hh * (INTER / 4);  // 704 float4 per row

    // Front-batch the full weight row: 22 independent LDG.128 up front (HBM).
    float4 u[22];
    #pragma unroll
    for (int j = 0; j < 22; j++)
        u[j] = ur[lane + 32 * j];

    float4* s_h4 = reinterpret_cast<float4*>(s_h);

    for (int pb = 0; pb < cnt; pb += CHUNK) {
        const int nch = (cnt - pb < CHUNK) ? (cnt - pb) : CHUNK;

        // Cooperative stage: 256 threads copy nch h-rows (coalesced, deep MLP).
        __syncthreads();                            // previous chunk consumed
        for (int i = tid; i < nch * (INTER / 4); i += 256) {
            const int pr = i / (INTER / 4);
            const int k  = i - pr * (INTER / 4);
            const float4* hr = reinterpret_cast<const float4*>(
                g_h + (size_t)s_pair[pb + pr] * INTER);
            s_h4[pr * (INTER / 4) + k] = hr[k];
        }
        __syncthreads();

        for (int p = 0; p < nch; p++) {
            const float4* hp = s_h4 + p * (INTER / 4);
            float a0 = 0.f, a1 = 0.f;
            #pragma unroll
            for (int j = 0; j < 22; j += 2) {
                a0 = dot4(u[j],     hp[lane + 32 * j],       a0);
                a1 = dot4(u[j + 1], hp[lane + 32 * (j + 1)], a1);
            }
            float acc = a0 + a1;
            #pragma unroll
            for (int off = 16; off; off >>= 1)
                acc += __shfl_xor_sync(0xFFFFFFFFu, acc, off);
            if (lane == 0)
                out[(size_t)s_pair[pb + p] * HID + hh] = acc;
        }
    }
}

// ---------------------------------------------------------------------------
extern "C" void kernel_launch(void* const* d_in, const int* in_sizes, int n_in,
                              void* d_out, int out_size)
{
    const float* x    = (const float*)d_in[0];
    const int*   eidx = (const int*)  d_in[1];
    const float* gate = (const float*)d_in[2];
    const float* up   = (const float*)d_in[3];
    const float* down = (const float*)d_in[4];
    float* out = (float*)d_out;

    dim3 g1(INTER / 32, NEXP);   // 88 x 8
    moe_phase1<<<g1, 256>>>(x, eidx, gate, down);

    dim3 g2(HID / 8, NEXP);      // 128 x 8
    moe_phase2<<<g2, 256>>>(eidx, up, out);
}

// round 11
// speedup vs baseline: 1.0851x; 1.0851x over previous
#include <cuda_runtime.h>

// MoE conditional FFN: T=16, TOP_K=2, E=8, H=1024, I=2816, fp32.
// Expert-major grouping: each used expert's weights stream from HBM once.
//
// R7: phase2 restructured to be SHAPE-IDENTICAL to phase1 (6.45 TB/s proven):
//  - grid (HID/32, NEXP) = 256 blocks -> single wave at 2 blocks/SM (296 slots)
//  - warp = 4 rows via rr loop: weight batch of row rr+1 overlaps compute tail
//    of row rr (this load/compute alternation is what phase1 has and every
//    prior phase2 lacked; R5/R6 warps did ONE batch then a long tail and died)
//  - h consumed from block-staged shared memory (45 KB chunk of <=4 pairs),
//    syncs only at chunk boundaries (outside the rr loop).

#define NTOK   16
#define TOPK   2
#define NPAIR  (NTOK * TOPK)       // 32
#define HID    1024
#define INTER  2816
#define NEXP   8

__device__ float g_h[NPAIR * INTER];   // 360 KB scratch

__device__ __forceinline__ float dot4(float4 a, float4 b, float acc) {
    acc = fmaf(a.x, b.x, acc);
    acc = fmaf(a.y, b.y, acc);
    acc = fmaf(a.z, b.z, acc);
    return fmaf(a.w, b.w, acc);
}

// ---------------------------------------------------------------------------
// Phase 1 (R1's proven version, 28.5us = 6.45 TB/s): gate & down GEMVs + SiLU.
// grid = (INTER/32, NEXP), block = 256 (8 warps). Warp handles 4 rows; per row
// preloads 8+8 float4 weights into registers; pair loop reads x from L1.
// ---------------------------------------------------------------------------
__global__ __launch_bounds__(256, 2)
void moe_phase1(const float* __restrict__ x,        // [T, H]
                const int*   __restrict__ eidx,     // [T, TOPK]
                const float* __restrict__ gate,     // [E, I, H]
                const float* __restrict__ down)     // [E, I, H]
{
    const int e = blockIdx.y;

    __shared__ int s_cnt;
    __shared__ int s_pair[NPAIR];
    if (threadIdx.x == 0) {
        int c = 0;
        #pragma unroll
        for (int i = 0; i < NPAIR; i++)
            if (eidx[i] == e) s_pair[c++] = i;
        s_cnt = c;
    }
    __syncthreads();
    const int cnt = s_cnt;
    if (cnt == 0) return;

    const int warp = threadIdx.x >> 5;
    const int lane = threadIdx.x & 31;
    const int row0 = blockIdx.x * 32 + warp * 4;

    const float4* gate4 = reinterpret_cast<const float4*>(gate + (size_t)e * INTER * HID);
    const float4* down4 = reinterpret_cast<const float4*>(down + (size_t)e * INTER * HID);

    for (int rr = 0; rr < 4; rr++) {
        const int row = row0 + rr;
        const float4* gr = gate4 + (size_t)row * (HID / 4);
        const float4* dr = down4 + (size_t)row * (HID / 4);

        float4 g4[8], d4[8];
        #pragma unroll
        for (int j = 0; j < 8; j++) {
            g4[j] = gr[lane + 32 * j];
            d4[j] = dr[lane + 32 * j];
        }

        for (int p = 0; p < cnt; p++) {
            const int pa = s_pair[p];
            const int t  = pa >> 1;
            const float4* xr = reinterpret_cast<const float4*>(x + (size_t)t * HID);

            float ag = 0.f, ad = 0.f;
            #pragma unroll
            for (int j = 0; j < 8; j++) {
                const float4 x4 = xr[lane + 32 * j];
                ag = dot4(g4[j], x4, ag);
                ad = dot4(d4[j], x4, ad);
            }
            #pragma unroll
            for (int off = 16; off; off >>= 1) {
                ag += __shfl_xor_sync(0xFFFFFFFFu, ag, off);
                ad += __shfl_xor_sync(0xFFFFFFFFu, ad, off);
            }
            if (lane == 0) {
                const float s = ag / (1.f + __expf(-ag));   // silu(gate)
                g_h[(size_t)pa * INTER + row] = s * ad;
            }
        }
    }
}

// ---------------------------------------------------------------------------
// Phase 2: out[pair,hh] = up[e,hh,:] . h[pair,:]
// grid = (HID/32, NEXP) = 256 blocks (single wave), block = 256 (8 warps).
// Chunk loop (<=4 pairs): stage h rows into smem (coalesced), then each warp
// runs a 4-row rr loop; per row it front-batches the full weight row into
// 22 float4 registers and consumes against smem h.
// ---------------------------------------------------------------------------
#define CHUNK 4

__global__ __launch_bounds__(256, 2)
void moe_phase2(const int*   __restrict__ eidx,     // [T, TOPK]
                const float* __restrict__ up,       // [E, H, I]
                float*       __restrict__ out)      // [T, TOPK, H]
{
    const int e = blockIdx.y;

    __shared__ float s_h[CHUNK * INTER];            // 45056 B
    __shared__ int s_cnt;
    __shared__ int s_pair[NPAIR];

    const int tid = threadIdx.x;
    if (tid == 0) {
        int c = 0;
        #pragma unroll
        for (int i = 0; i < NPAIR; i++)
            if (eidx[i] == e) s_pair[c++] = i;
        s_cnt = c;
    }
    __syncthreads();
    const int cnt = s_cnt;
    if (cnt == 0) return;

    const int warp = tid >> 5;
    const int lane = tid & 31;
    const int row0 = blockIdx.x * 32 + warp * 4;

    const float4* up4 = reinterpret_cast<const float4*>(up + (size_t)e * HID * INTER);
    float4* s_h4 = reinterpret_cast<float4*>(s_h);

    for (int pb = 0; pb < cnt; pb += CHUNK) {
        const int nch = (cnt - pb < CHUNK) ? (cnt - pb) : CHUNK;

        // Cooperative stage: 256 threads copy nch h-rows from L2 (coalesced).
        __syncthreads();                            // previous chunk consumed
        for (int i = tid; i < nch * (INTER / 4); i += 256) {
            const int pr = i / (INTER / 4);
            const int k  = i - pr * (INTER / 4);
            const float4* hr = reinterpret_cast<const float4*>(
                g_h + (size_t)s_pair[pb + pr] * INTER);
            s_h4[pr * (INTER / 4) + k] = hr[k];
        }
        __syncthreads();

        // Phase1-style rr loop: alternate weight-batch load / compute so the
        // scoreboard overlaps row rr+1's HBM batch with row rr's tail.
        for (int rr = 0; rr < 4; rr++) {
            const int row = row0 + rr;
            const float4* ur = up4 + (size_t)row * (INTER / 4);

            float4 u[22];                           // front-batched weight row
            #pragma unroll
            for (int j = 0; j < 22; j++)
                u[j] = ur[lane + 32 * j];

            for (int p = 0; p < nch; p++) {
                const float4* hp = s_h4 + p * (INTER / 4);
                float a0 = 0.f, a1 = 0.f;
                #pragma unroll
                for (int j = 0; j < 22; j += 2) {
                    a0 = dot4(u[j],     hp[lane + 32 * j],       a0);
                    a1 = dot4(u[j + 1], hp[lane + 32 * (j + 1)], a1);
                }
                float acc = a0 + a1;
                #pragma unroll
                for (int off = 16; off; off >>= 1)
                    acc += __shfl_xor_sync(0xFFFFFFFFu, acc, off);
                if (lane == 0)
                    out[(size_t)s_pair[pb + p] * HID + row] = acc;
            }
        }
    }
}

// ---------------------------------------------------------------------------
extern "C" void kernel_launch(void* const* d_in, const int* in_sizes, int n_in,
                              void* d_out, int out_size)
{
    const float* x    = (const float*)d_in[0];
    const int*   eidx = (const int*)  d_in[1];
    const float* gate = (const float*)d_in[2];
    const float* up   = (const float*)d_in[3];
    const float* down = (const float*)d_in[4];
    float* out = (float*)d_out;

    dim3 g1(INTER / 32, NEXP);   // 88 x 8
    moe_phase1<<<g1, 256>>>(x, eidx, gate, down);

    dim3 g2(HID / 32, NEXP);     // 32 x 8 = 256 blocks, single wave
    moe_phase2<<<g2, 256>>>(eidx, up, out);
}